// round 1
// baseline (speedup 1.0000x reference)
#include <cuda_runtime.h>
#include <math.h>

// ConLoss: NT-Xent contrastive loss.
// z = normalize(concat(h1,h2)) [8192,512]; sim = z z^T; T=0.5
// loss_i = -sim[i, i^4096]/T + log( sum_{j!=i} exp(sim_ij/T) ); out = mean_i loss_i

#define NROWS 8192
#define HALF  4096
#define D     512

#define BM 128
#define BN 128
#define BK 32
#define CGRPS 4
#define CT_PER (NROWS / BN / CGRPS)   // 16 column tiles per block

__device__ float g_zn[NROWS * D];   // normalized rows
__device__ float g_S[NROWS];        // sum_{j!=i} exp(2*sim_ij)
__device__ float g_pos[NROWS];      // sim[i, i^HALF]

// Pure-FMA exp(x) for |x| <= ~3 (keeps MUFU idle). rel err ~2e-6.
__device__ __forceinline__ float fast_exp(float x) {
    float t = x * 1.4426950408889634f;           // x * log2(e)
    float m = t + 12582912.0f;                   // round-to-nearest via magic number
    float r = m - 12582912.0f;
    float f = t - r;                             // frac in [-0.5, 0.5]
    int   e = __float_as_int(m) - 0x4B400000;    // integer part
    float u = f * 0.6931471805599453f;           // frac * ln2, |u| <= 0.347
    float p = fmaf(u, 8.3333333e-3f, 4.1666667e-2f);
    p = fmaf(p, u, 1.6666667e-1f);
    p = fmaf(p, u, 0.5f);
    p = fmaf(p, u, 1.0f);
    p = fmaf(p, u, 1.0f);
    return p * __int_as_float((e + 127) << 23);
}

__global__ void init_kernel() {
    int i = blockIdx.x * blockDim.x + threadIdx.x;
    if (i < NROWS) g_S[i] = 0.0f;
}

// One warp per row: compute 1/max(||z||, eps) and write normalized row.
__global__ void norm_kernel(const float* __restrict__ a, const float* __restrict__ b) {
    int gw   = (blockIdx.x * blockDim.x + threadIdx.x) >> 5;
    int lane = threadIdx.x & 31;
    if (gw >= NROWS) return;
    const float* src = (gw < HALF) ? (a + (size_t)gw * D) : (b + (size_t)(gw - HALF) * D);
    const float4* s4 = (const float4*)src;
    float4 v[4];
    float ss = 0.0f;
#pragma unroll
    for (int l = 0; l < 4; l++) {
        v[l] = s4[lane + l * 32];
        ss += v[l].x * v[l].x + v[l].y * v[l].y + v[l].z * v[l].z + v[l].w * v[l].w;
    }
#pragma unroll
    for (int m = 16; m; m >>= 1) ss += __shfl_xor_sync(0xffffffffu, ss, m);
    float inv = 1.0f / fmaxf(sqrtf(ss), 1e-8f);
    float4* d4 = (float4*)(g_zn + (size_t)gw * D);
#pragma unroll
    for (int l = 0; l < 4; l++) {
        float4 w = v[l];
        w.x *= inv; w.y *= inv; w.z *= inv; w.w *= inv;
        d4[lane + l * 32] = w;
    }
}

// 128x128 tile GEMM (8x8 per thread, 256 threads) fused with exp row-sums.
// grid = (64 row tiles, 4 column groups); each block scans 16 column tiles,
// keeping per-row exp-sums in registers; one atomicAdd per row at the end.
__global__ __launch_bounds__(256, 2) void gemm_kernel() {
    __shared__ float As[BK][BM + 8];
    __shared__ float Bs[BK][BN + 8];
    const int tid = threadIdx.x;
    const int tx = tid & 15;
    const int ty = tid >> 4;
    const int rt = blockIdx.x;
    const int cg = blockIdx.y;
    const int row_base = rt * BM;

    float rowsum[8];
#pragma unroll
    for (int i = 0; i < 8; i++) rowsum[i] = 0.0f;

    for (int ct = cg * CT_PER; ct < (cg + 1) * CT_PER; ct++) {
        const int col_base = ct * BN;
        float acc[8][8];
#pragma unroll
        for (int i = 0; i < 8; i++)
#pragma unroll
            for (int j = 0; j < 8; j++) acc[i][j] = 0.0f;

        for (int kc = 0; kc < D; kc += BK) {
            const float* Ap = g_zn + (size_t)row_base * D + kc;
            const float* Bp = g_zn + (size_t)col_base * D + kc;
#pragma unroll
            for (int l = 0; l < 4; l++) {
                int idx = tid + l * 256;       // 0..1023 float4s (128 rows x 8 f4)
                int m   = idx >> 3;
                int k4  = (idx & 7) << 2;
                float4 va = *(const float4*)(Ap + m * D + k4);
                As[k4 + 0][m] = va.x; As[k4 + 1][m] = va.y;
                As[k4 + 2][m] = va.z; As[k4 + 3][m] = va.w;
                float4 vb = *(const float4*)(Bp + m * D + k4);
                Bs[k4 + 0][m] = vb.x; Bs[k4 + 1][m] = vb.y;
                Bs[k4 + 2][m] = vb.z; Bs[k4 + 3][m] = vb.w;
            }
            __syncthreads();
#pragma unroll
            for (int k = 0; k < BK; k++) {
                float a[8], b[8];
                *(float4*)&a[0] = *(const float4*)&As[k][ty * 8];
                *(float4*)&a[4] = *(const float4*)&As[k][ty * 8 + 4];
                *(float4*)&b[0] = *(const float4*)&Bs[k][tx * 8];
                *(float4*)&b[4] = *(const float4*)&Bs[k][tx * 8 + 4];
#pragma unroll
                for (int i = 0; i < 8; i++)
#pragma unroll
                    for (int j = 0; j < 8; j++)
                        acc[i][j] = fmaf(a[i], b[j], acc[i][j]);
            }
            __syncthreads();
        }

        // epilogue: capture positives, exclude diagonal, accumulate exp-sums
#pragma unroll
        for (int i = 0; i < 8; i++) {
            int r = row_base + ty * 8 + i;
#pragma unroll
            for (int j = 0; j < 8; j++) {
                int c = col_base + tx * 8 + j;
                float s = acc[i][j];
                if (c == (r ^ HALF)) g_pos[r] = s;
                float e = (c == r) ? 0.0f : fast_exp(s * 2.0f);  // /T, T=0.5
                rowsum[i] += e;
            }
        }
    }

    // reduce the 16 tx-partials per row (lanes differing only in bits 0..3)
#pragma unroll
    for (int i = 0; i < 8; i++) {
        float v = rowsum[i];
        v += __shfl_xor_sync(0xffffffffu, v, 8);
        v += __shfl_xor_sync(0xffffffffu, v, 4);
        v += __shfl_xor_sync(0xffffffffu, v, 2);
        v += __shfl_xor_sync(0xffffffffu, v, 1);
        if (tx == 0) atomicAdd(&g_S[row_base + ty * 8 + i], v);
    }
}

__global__ void loss_kernel(float* __restrict__ out) {
    __shared__ float red[256];
    int tid = threadIdx.x;
    float acc = 0.0f;
    for (int i = tid; i < NROWS; i += 256)
        acc += -2.0f * g_pos[i] + logf(g_S[i]);
    red[tid] = acc;
    __syncthreads();
    for (int s = 128; s; s >>= 1) {
        if (tid < s) red[tid] += red[tid + s];
        __syncthreads();
    }
    if (tid == 0) out[0] = red[0] * (1.0f / NROWS);
}

extern "C" void kernel_launch(void* const* d_in, const int* in_sizes, int n_in,
                              void* d_out, int out_size) {
    const float* a = (const float*)d_in[0];
    const float* b = (const float*)d_in[1];
    (void)in_sizes; (void)n_in; (void)out_size;

    init_kernel<<<32, 256>>>();
    norm_kernel<<<NROWS / 8, 256>>>(a, b);
    dim3 grid(NROWS / BM, CGRPS);
    gemm_kernel<<<grid, 256>>>();
    loss_kernel<<<1, 256>>>((float*)d_out);
}

// round 4
// speedup vs baseline: 7.6695x; 7.6695x over previous
#include <cuda_runtime.h>
#include <cuda_bf16.h>
#include <math.h>
#include <stdint.h>

// ConLoss (NT-Xent): z = normalize(concat(h1,h2)) [8192,512]; sim = z z^T; T=0.5
// loss_i = -2*sim[i, i^4096] + log(sum_{j!=i} exp(2*sim_ij)); out = mean.
// Round 3: bf16 mma.sync (HMMA) GEMM — tcgen05 unavailable (harness emits
// compute_103 PTX). A tile resident in SMEM, cp.async-pipelined B, fused exp.

#define NROWS 8192
#define HALF  4096
#define D     512

#define BM 128
#define BN 128
#define BK 64
#define NCHUNK (D / BK)            // 8 chunks per column tile
#define CGRPS 2
#define CT_PER (NROWS / BN / CGRPS)  // 32 column tiles per CTA

#define CHUNK_BYTES (128 * 128)    // 16 KB (128 rows x 128B)
#define SMEM_A 0                   // 8 chunks resident = 128 KB
#define SMEM_B (NCHUNK * CHUNK_BYTES)   // 131072, 2 x 16 KB double buffer
#define SMEM_TOTAL (SMEM_B + 2 * CHUNK_BYTES)  // 163840

__device__ __align__(16) __nv_bfloat16 g_zbf[NROWS * D];
__device__ float g_S[NROWS];
__device__ float g_pos[NROWS];

// ---------------- helpers ----------------
__device__ __forceinline__ uint32_t smem_u32(const void* p) {
    uint32_t a;
    asm("{ .reg .u64 t; cvta.to.shared.u64 t, %1; cvt.u32.u64 %0, t; }" : "=r"(a) : "l"(p));
    return a;
}
__device__ __forceinline__ uint32_t SWZ(uint32_t off) {   // SW128 swizzle
    return off ^ ((off >> 3) & 0x70);
}
__device__ __forceinline__ void cp16(uint32_t dst, const void* src) {
    asm volatile("cp.async.cg.shared.global [%0], [%1], 16;" :: "r"(dst), "l"(src));
}
#define CP_COMMIT() asm volatile("cp.async.commit_group;" ::: "memory")
#define CP_WAIT(n)  asm volatile("cp.async.wait_group %0;" :: "n"(n) : "memory")

__device__ __forceinline__ void ldmx4(uint32_t* r, uint32_t addr) {
    asm volatile("ldmatrix.sync.aligned.m8n8.x4.shared.b16 {%0,%1,%2,%3}, [%4];"
                 : "=r"(r[0]), "=r"(r[1]), "=r"(r[2]), "=r"(r[3]) : "r"(addr));
}
__device__ __forceinline__ void mma16816(float* c, const uint32_t* a, const uint32_t* b) {
    asm volatile("mma.sync.aligned.m16n8k16.row.col.f32.bf16.bf16.f32 "
                 "{%0,%1,%2,%3}, {%4,%5,%6,%7}, {%8,%9}, {%0,%1,%2,%3};"
                 : "+f"(c[0]), "+f"(c[1]), "+f"(c[2]), "+f"(c[3])
                 : "r"(a[0]), "r"(a[1]), "r"(a[2]), "r"(a[3]), "r"(b[0]), "r"(b[1]));
}

// Pure-FMA exp(x) for |x| <= ~3 (keeps MUFU idle). rel err ~2e-6.
__device__ __forceinline__ float fast_exp(float x) {
    float t = x * 1.4426950408889634f;
    float m = t + 12582912.0f;
    float r = m - 12582912.0f;
    float f = t - r;
    int   e = __float_as_int(m) - 0x4B400000;
    float u = f * 0.6931471805599453f;
    float p = fmaf(u, 8.3333333e-3f, 4.1666667e-2f);
    p = fmaf(p, u, 1.6666667e-1f);
    p = fmaf(p, u, 0.5f);
    p = fmaf(p, u, 1.0f);
    p = fmaf(p, u, 1.0f);
    return p * __int_as_float((e + 127) << 23);
}

// ---------------- kernels ----------------
__global__ void init_kernel() {
    int i = blockIdx.x * blockDim.x + threadIdx.x;
    if (i < NROWS) g_S[i] = 0.0f;
}

// One warp per row: normalize in fp32, write bf16.
__global__ void norm_kernel(const float* __restrict__ a, const float* __restrict__ b) {
    int gw   = (blockIdx.x * blockDim.x + threadIdx.x) >> 5;
    int lane = threadIdx.x & 31;
    if (gw >= NROWS) return;
    const float* src = (gw < HALF) ? (a + (size_t)gw * D) : (b + (size_t)(gw - HALF) * D);
    const float4* s4 = (const float4*)src;
    float4 v[4];
    float ss = 0.0f;
#pragma unroll
    for (int l = 0; l < 4; l++) {
        v[l] = s4[lane + l * 32];
        ss += v[l].x * v[l].x + v[l].y * v[l].y + v[l].z * v[l].z + v[l].w * v[l].w;
    }
#pragma unroll
    for (int m = 16; m; m >>= 1) ss += __shfl_xor_sync(0xffffffffu, ss, m);
    float inv = 1.0f / fmaxf(sqrtf(ss), 1e-8f);
    __nv_bfloat162* d2 = (__nv_bfloat162*)(g_zbf + (size_t)gw * D);
#pragma unroll
    for (int l = 0; l < 4; l++) {
        float4 w = v[l];
        d2[2 * lane + 0 + 64 * l] = __floats2bfloat162_rn(w.x * inv, w.y * inv);
        d2[2 * lane + 1 + 64 * l] = __floats2bfloat162_rn(w.z * inv, w.w * inv);
    }
}

// grid (64 row tiles, 2 col groups), 256 threads = 8 warps (4 row x 2 col).
__global__ __launch_bounds__(256, 1) void gemm_kernel() {
    extern __shared__ __align__(1024) char smem[];
    const uint32_t sb = smem_u32(smem);
    const int tid  = threadIdx.x;
    const int wid  = tid >> 5;
    const int lane = tid & 31;
    const int wm = wid & 3;        // row warp 0..3 (32 rows each)
    const int wn = wid >> 2;       // col warp 0..1 (64 cols each)
    const int row_base = blockIdx.x * BM;
    const int cg = blockIdx.y;

    const uint4* Z4 = (const uint4*)g_zbf;

    // Issue resident A tile loads: 8192 uint4, SW128 per 16KB chunk.
#pragma unroll
    for (int l = 0; l < 32; l++) {
        int idx = tid + l * 256;
        int c = idx >> 10, w = idx & 1023, row = w >> 3, g = w & 7;
        cp16(sb + SMEM_A + c * CHUNK_BYTES + SWZ(row * 128 + g * 16),
             Z4 + (size_t)(row_base + row) * 64 + c * 8 + g);
    }
    // Issue first B chunk (ct=0, kc=0) into buffer 0.
    {
        const int col_base = cg * CT_PER * BN;
#pragma unroll
        for (int l = 0; l < 4; l++) {
            int idx = tid + l * 256;
            int row = idx >> 3, g = idx & 7;
            cp16(sb + SMEM_B + SWZ(row * 128 + g * 16),
                 Z4 + (size_t)(col_base + row) * 64 + g);
        }
    }
    CP_COMMIT();

    // lane-dependent ldmatrix address components
    const int a_row0 = wm * 32 + (lane & 15);
    const int a_cb   = (lane >> 4) * 16;
    const int b_row0 = wn * 64 + (lane & 7) + ((lane & 16) ? 8 : 0);
    const int b_cb   = (lane & 8) ? 16 : 0;

    // epilogue mapping
    const int ep_r0 = row_base + wm * 32 + (lane >> 2);  // +h*8 +mf*16
    const int ep_c0 = (lane & 3) * 2;

    float rowsum[2][2];   // [mf][h]
    rowsum[0][0] = rowsum[0][1] = rowsum[1][0] = rowsum[1][1] = 0.0f;

    for (int ct = 0; ct < CT_PER; ct++) {
        const int col_base = (cg * CT_PER + ct) * BN;
        float c[2][8][4];
#pragma unroll
        for (int mf = 0; mf < 2; mf++)
#pragma unroll
            for (int nf = 0; nf < 8; nf++)
#pragma unroll
                for (int e = 0; e < 4; e++) c[mf][nf][e] = 0.0f;

        for (int kc = 0; kc < NCHUNK; kc++) {
            const int ic = ct * NCHUNK + kc;
            // prefetch next chunk (possibly next ct's chunk 0)
            const int in = ic + 1;
            if (in < CT_PER * NCHUNK) {
                const int nct = in >> 3, nkc = in & 7;
                const int ncol = (cg * CT_PER + nct) * BN;
#pragma unroll
                for (int l = 0; l < 4; l++) {
                    int idx = tid + l * 256;
                    int row = idx >> 3, g = idx & 7;
                    cp16(sb + SMEM_B + (in & 1) * CHUNK_BYTES + SWZ(row * 128 + g * 16),
                         Z4 + (size_t)(ncol + row) * 64 + nkc * 8 + g);
                }
                CP_COMMIT();
                CP_WAIT(1);
            } else {
                CP_WAIT(0);
            }
            __syncthreads();

            const uint32_t Ab = sb + SMEM_A + kc * CHUNK_BYTES;
            const uint32_t Bb = sb + SMEM_B + (ic & 1) * CHUNK_BYTES;
#pragma unroll
            for (int k16 = 0; k16 < 4; k16++) {
                const int cb = k16 * 32;
                uint32_t af[2][4], bf[4][4];
#pragma unroll
                for (int mf = 0; mf < 2; mf++)
                    ldmx4(af[mf], Ab + SWZ((a_row0 + mf * 16) * 128 + cb + a_cb));
#pragma unroll
                for (int nf2 = 0; nf2 < 4; nf2++)
                    ldmx4(bf[nf2], Bb + SWZ((b_row0 + nf2 * 16) * 128 + cb + b_cb));
#pragma unroll
                for (int mf = 0; mf < 2; mf++)
#pragma unroll
                    for (int nf2 = 0; nf2 < 4; nf2++) {
                        mma16816(c[mf][nf2 * 2 + 0], af[mf], &bf[nf2][0]);
                        mma16816(c[mf][nf2 * 2 + 1], af[mf], &bf[nf2][2]);
                    }
            }
            __syncthreads();
        }

        // epilogue: positives, diagonal exclusion, exp row-sums (regs only;
        // next tile's first B chunk is already in flight)
#pragma unroll
        for (int mf = 0; mf < 2; mf++)
#pragma unroll
            for (int h = 0; h < 2; h++) {
                const int r = ep_r0 + mf * 16 + h * 8;
                float acc = 0.0f;
#pragma unroll
                for (int nf = 0; nf < 8; nf++)
#pragma unroll
                    for (int e = 0; e < 2; e++) {
                        const int cidx = col_base + wn * 64 + nf * 8 + ep_c0 + e;
                        const float sv = c[mf][nf][h * 2 + e];
                        if (cidx == (r ^ HALF)) g_pos[r] = sv;
                        acc += (cidx == r) ? 0.0f : fast_exp(sv * 2.0f);
                    }
                rowsum[mf][h] += acc;
            }
    }

    // reduce across the 4 lanes sharing a row, one atomic per row per warp
#pragma unroll
    for (int mf = 0; mf < 2; mf++)
#pragma unroll
        for (int h = 0; h < 2; h++) {
            float v = rowsum[mf][h];
            v += __shfl_xor_sync(0xffffffffu, v, 1);
            v += __shfl_xor_sync(0xffffffffu, v, 2);
            if ((lane & 3) == 0) atomicAdd(&g_S[ep_r0 + mf * 16 + h * 8], v);
        }
}

__global__ void loss_kernel(float* __restrict__ out) {
    __shared__ float red[32];
    int tid = threadIdx.x;
    float acc = 0.0f;
    for (int i = tid; i < NROWS; i += 1024)
        acc += -2.0f * g_pos[i] + logf(g_S[i]);
#pragma unroll
    for (int m = 16; m; m >>= 1) acc += __shfl_xor_sync(0xffffffffu, acc, m);
    if ((tid & 31) == 0) red[tid >> 5] = acc;
    __syncthreads();
    if (tid < 32) {
        float v = red[tid];
#pragma unroll
        for (int m = 16; m; m >>= 1) v += __shfl_xor_sync(0xffffffffu, v, m);
        if (tid == 0) out[0] = v * (1.0f / NROWS);
    }
}

extern "C" void kernel_launch(void* const* d_in, const int* in_sizes, int n_in,
                              void* d_out, int out_size) {
    const float* a = (const float*)d_in[0];
    const float* b = (const float*)d_in[1];
    (void)in_sizes; (void)n_in; (void)out_size;

    cudaFuncSetAttribute(gemm_kernel, cudaFuncAttributeMaxDynamicSharedMemorySize, SMEM_TOTAL);

    init_kernel<<<32, 256>>>();
    norm_kernel<<<NROWS / 8, 256>>>(a, b);
    dim3 grid(NROWS / BM, CGRPS);
    gemm_kernel<<<grid, 256, SMEM_TOTAL>>>();
    loss_kernel<<<1, 1024>>>((float*)d_out);
}

// round 9
// speedup vs baseline: 8.7810x; 1.1449x over previous
#include <cuda_runtime.h>
#include <cuda_bf16.h>
#include <math.h>
#include <stdint.h>

// ConLoss (NT-Xent): z = normalize(concat(h1,h2)) [8192,512]; sim = z z^T; T=0.5
// loss_i = -2*sim[i,i^4096] + log(sum_{j!=i} exp(2*sim_ij)); out = mean.
// Round 5: e4m3 mma.sync (2x tensor rate, half smem traffic), z scaled by 16,
// 3-stage single-barrier cp.async pipeline, loss fused into gemm (last CTA).

#define NROWS 8192
#define HALF  4096
#define D     512

#define BM 128
#define BN 256
#define BK 128                       // fp8 elems per chunk = 128 bytes/row
#define NKC (D / BK)                 // 4 chunks per column tile
#define CGRPS 2
#define CT_PER (NROWS / BN / CGRPS)  // 16 column tiles per CTA
#define TC (CT_PER * NKC)            // 64 chunks total
#define TOTAL_CTAS ((NROWS / BM) * CGRPS)  // 128

#define ACH_BYTES (128 * 128)        // 16 KB A chunk
#define BST_BYTES (BN * 128)         // 32 KB B stage
#define SMEM_A 0                     // 4 chunks resident = 64 KB
#define SMEM_B (NKC * ACH_BYTES)     // 65536; 3 stages of 32 KB
#define SMEM_TOTAL (SMEM_B + 3 * BST_BYTES)  // 163840

// exp(2*sim) = 2^(acc * 2*log2e/256), acc = 256*sim
#define EXP_SCALE 0.0112710550f
#define POS_SCALE 0.0078125f         // 2/256

__device__ __align__(16) uint8_t g_z8[NROWS * D];
__device__ float g_S[NROWS];
__device__ float g_pos[NROWS];       // raw acc = 256*sim at positive pair
__device__ unsigned int g_cnt = 0;

// ---------------- helpers ----------------
__device__ __forceinline__ uint32_t smem_u32(const void* p) {
    uint32_t a;
    asm("{ .reg .u64 t; cvta.to.shared.u64 t, %1; cvt.u32.u64 %0, t; }" : "=r"(a) : "l"(p));
    return a;
}
__device__ __forceinline__ uint32_t SWZ(uint32_t off) {   // SW128 swizzle
    return off ^ ((off >> 3) & 0x70);
}
__device__ __forceinline__ void cp16(uint32_t dst, const void* src) {
    asm volatile("cp.async.cg.shared.global [%0], [%1], 16;" :: "r"(dst), "l"(src));
}
#define CP_COMMIT() asm volatile("cp.async.commit_group;" ::: "memory")
#define CP_WAIT(n)  asm volatile("cp.async.wait_group %0;" :: "n"(n) : "memory")

__device__ __forceinline__ void ldmx4(uint32_t* r, uint32_t addr) {
    asm volatile("ldmatrix.sync.aligned.m8n8.x4.shared.b16 {%0,%1,%2,%3}, [%4];"
                 : "=r"(r[0]), "=r"(r[1]), "=r"(r[2]), "=r"(r[3]) : "r"(addr));
}
__device__ __forceinline__ void mma_fp8(float* c, const uint32_t* a, const uint32_t* b) {
    asm volatile("mma.sync.aligned.m16n8k32.row.col.f32.e4m3.e4m3.f32 "
                 "{%0,%1,%2,%3}, {%4,%5,%6,%7}, {%8,%9}, {%0,%1,%2,%3};"
                 : "+f"(c[0]), "+f"(c[1]), "+f"(c[2]), "+f"(c[3])
                 : "r"(a[0]), "r"(a[1]), "r"(a[2]), "r"(a[3]), "r"(b[0]), "r"(b[1]));
}
__device__ __forceinline__ float ex2f(float x) {
    float y;
    asm("ex2.approx.f32 %0, %1;" : "=f"(y) : "f"(x));
    return y;
}
__device__ __forceinline__ uint32_t pack_e4m3(float f0, float f1, float f2, float f3) {
    uint16_t lo, hi;
    asm("cvt.rn.satfinite.e4m3x2.f32 %0, %1, %2;" : "=h"(lo) : "f"(f1), "f"(f0));
    asm("cvt.rn.satfinite.e4m3x2.f32 %0, %1, %2;" : "=h"(hi) : "f"(f3), "f"(f2));
    return (uint32_t)lo | ((uint32_t)hi << 16);
}

// ---------------- kernels ----------------
// One warp per row: normalize, scale by 16, write e4m3. Also zeroes g_S.
__global__ void norm_kernel(const float* __restrict__ a, const float* __restrict__ b) {
    int gt = blockIdx.x * blockDim.x + threadIdx.x;
    if (gt < NROWS) g_S[gt] = 0.0f;
    int gw   = gt >> 5;
    int lane = threadIdx.x & 31;
    if (gw >= NROWS) return;
    const float* src = (gw < HALF) ? (a + (size_t)gw * D) : (b + (size_t)(gw - HALF) * D);
    const float4* s4 = (const float4*)src;
    float4 v[4];
    float ss = 0.0f;
#pragma unroll
    for (int l = 0; l < 4; l++) {
        v[l] = s4[lane + l * 32];
        ss += v[l].x * v[l].x + v[l].y * v[l].y + v[l].z * v[l].z + v[l].w * v[l].w;
    }
#pragma unroll
    for (int m = 16; m; m >>= 1) ss += __shfl_xor_sync(0xffffffffu, ss, m);
    float inv = 16.0f / fmaxf(sqrtf(ss), 1e-8f);
    uint32_t* d32 = (uint32_t*)(g_z8 + (size_t)gw * D);
#pragma unroll
    for (int l = 0; l < 4; l++) {
        float4 w = v[l];
        d32[lane + 32 * l] = pack_e4m3(w.x * inv, w.y * inv, w.z * inv, w.w * inv);
    }
}

// grid (64 row tiles, 2 col groups), 256 threads = 8 warps (4 row x 2 col).
// Warp tile 32x128. Last CTA out computes the final loss.
__global__ __launch_bounds__(256, 1) void gemm_kernel(float* __restrict__ out) {
    extern __shared__ __align__(1024) char smem[];
    const uint32_t sb = smem_u32(smem);
    const int tid  = threadIdx.x;
    const int wid  = tid >> 5;
    const int lane = tid & 31;
    const int wm = wid & 3;        // row warp: 32 rows
    const int wn = wid >> 2;       // col warp: 128 cols
    const int row_base = blockIdx.x * BM;
    const int cg = blockIdx.y;

    const uint4* Z4 = (const uint4*)g_z8;   // 32 uint4 per row

    // Resident A tile: 64 KB = 4096 cp16 (16/thread), SW128 per 16KB chunk.
#pragma unroll
    for (int l = 0; l < 16; l++) {
        int idx = tid + l * 256;
        int c = idx >> 10, w = idx & 1023, row = w >> 3, g = w & 7;
        cp16(sb + SMEM_A + c * ACH_BYTES + SWZ(row * 128 + g * 16),
             Z4 + (size_t)(row_base + row) * 32 + c * 8 + g);
    }
    // First two B chunks.
    const int cb0 = cg * CT_PER * BN;
#pragma unroll
    for (int l = 0; l < 8; l++) {
        int idx = tid + l * 256;
        int row = idx >> 3, g = idx & 7;
        cp16(sb + SMEM_B + SWZ(row * 128 + g * 16),
             Z4 + (size_t)(cb0 + row) * 32 + g);
    }
    CP_COMMIT();   // group: A + chunk0
#pragma unroll
    for (int l = 0; l < 8; l++) {
        int idx = tid + l * 256;
        int row = idx >> 3, g = idx & 7;
        cp16(sb + SMEM_B + BST_BYTES + SWZ(row * 128 + g * 16),
             Z4 + (size_t)(cb0 + row) * 32 + 8 + g);
    }
    CP_COMMIT();   // group: chunk1

    // ldmatrix lane addressing (fragment layouts for m16n8k32 e4m3)
    const int a_row0 = wm * 32 + (lane & 15);
    const int a_cb   = (lane >> 4) * 16;
    const int b_row0 = wn * 128 + (lane & 7) + ((lane & 16) ? 8 : 0);
    const int b_cb   = (lane & 8) ? 16 : 0;

    // epilogue mapping
    const int ep_r0 = row_base + wm * 32 + (lane >> 2);  // + mf*16 + h*8
    const int ep_c0 = (lane & 3) * 2;

    float rowsum[2][2];
    rowsum[0][0] = rowsum[0][1] = rowsum[1][0] = rowsum[1][1] = 0.0f;

    int ic = 0;
    for (int ct = 0; ct < CT_PER; ct++) {
        const int col_base = (cg * CT_PER + ct) * BN;
        float c[2][16][4];
#pragma unroll
        for (int mf = 0; mf < 2; mf++)
#pragma unroll
            for (int nf = 0; nf < 16; nf++)
#pragma unroll
                for (int e = 0; e < 4; e++) c[mf][nf][e] = 0.0f;

#pragma unroll 1
        for (int kc = 0; kc < NKC; kc++, ic++) {
            CP_WAIT(1);            // chunk ic resident
            __syncthreads();       // publish + guard stage reuse (dist 2, 3 stages)
            const int inx = ic + 2;
            if (inx < TC) {
                const int nct = inx >> 2, nkc = inx & 3;
                const int ncol = (cg * CT_PER + nct) * BN;
                const uint32_t dst = sb + SMEM_B + (inx % 3) * BST_BYTES;
#pragma unroll
                for (int l = 0; l < 8; l++) {
                    int idx = tid + l * 256;
                    int row = idx >> 3, g = idx & 7;
                    cp16(dst + SWZ(row * 128 + g * 16),
                         Z4 + (size_t)(ncol + row) * 32 + nkc * 8 + g);
                }
                CP_COMMIT();
            }

            const uint32_t Ab = sb + SMEM_A + kc * ACH_BYTES;
            const uint32_t Bb = sb + SMEM_B + (ic % 3) * BST_BYTES;
#pragma unroll
            for (int k32 = 0; k32 < 4; k32++) {
                const int cb = k32 * 32;
                uint32_t af[2][4];
#pragma unroll
                for (int mf = 0; mf < 2; mf++)
                    ldmx4(af[mf], Ab + SWZ((a_row0 + mf * 16) * 128 + cb + a_cb));
#pragma unroll
                for (int half = 0; half < 2; half++) {
                    uint32_t bf[4][4];
#pragma unroll
                    for (int q = 0; q < 4; q++)
                        ldmx4(bf[q], Bb + SWZ((b_row0 + (half * 4 + q) * 16) * 128 + cb + b_cb));
#pragma unroll
                    for (int mf = 0; mf < 2; mf++)
#pragma unroll
                        for (int q = 0; q < 4; q++) {
                            mma_fp8(c[mf][(half * 4 + q) * 2 + 0], af[mf], &bf[q][0]);
                            mma_fp8(c[mf][(half * 4 + q) * 2 + 1], af[mf], &bf[q][2]);
                        }
                }
            }
        }

        // epilogue: positives, diagonal exclusion, exp row-sums (MUFU ex2)
#pragma unroll
        for (int mf = 0; mf < 2; mf++)
#pragma unroll
            for (int h = 0; h < 2; h++) {
                const int r = ep_r0 + mf * 16 + h * 8;
                float acc = 0.0f;
#pragma unroll
                for (int nf = 0; nf < 16; nf++)
#pragma unroll
                    for (int e = 0; e < 2; e++) {
                        const int cidx = col_base + wn * 128 + nf * 8 + ep_c0 + e;
                        const float sv = c[mf][nf][h * 2 + e];
                        if (cidx == (r ^ HALF)) g_pos[r] = sv;
                        acc += (cidx == r) ? 0.0f : ex2f(sv * EXP_SCALE);
                    }
                rowsum[mf][h] += acc;
            }
    }

    // reduce the 4 lanes sharing each row; one atomic per row per warp
#pragma unroll
    for (int mf = 0; mf < 2; mf++)
#pragma unroll
        for (int h = 0; h < 2; h++) {
            float v = rowsum[mf][h];
            v += __shfl_xor_sync(0xffffffffu, v, 1);
            v += __shfl_xor_sync(0xffffffffu, v, 2);
            if ((lane & 3) == 0) atomicAdd(&g_S[ep_r0 + mf * 16 + h * 8], v);
        }

    // ---- fused final loss: last CTA to finish reduces g_S / g_pos ----
    __threadfence();
    __shared__ unsigned int s_last;
    __syncthreads();
    if (tid == 0) s_last = atomicAdd(&g_cnt, 1u);
    __syncthreads();
    if (s_last == TOTAL_CTAS - 1) {
        __threadfence();
        float acc = 0.0f;
        for (int i = tid; i < NROWS; i += 256)
            acc += -POS_SCALE * g_pos[i] + logf(g_S[i]);
#pragma unroll
        for (int m = 16; m; m >>= 1) acc += __shfl_xor_sync(0xffffffffu, acc, m);
        __shared__ float red[8];
        if (lane == 0) red[wid] = acc;
        __syncthreads();
        if (tid == 0) {
            float v = 0.0f;
#pragma unroll
            for (int w = 0; w < 8; w++) v += red[w];
            out[0] = v * (1.0f / NROWS);
            g_cnt = 0;   // reset for next graph replay
        }
    }
}

extern "C" void kernel_launch(void* const* d_in, const int* in_sizes, int n_in,
                              void* d_out, int out_size) {
    const float* a = (const float*)d_in[0];
    const float* b = (const float*)d_in[1];
    (void)in_sizes; (void)n_in; (void)out_size;

    cudaFuncSetAttribute(gemm_kernel, cudaFuncAttributeMaxDynamicSharedMemorySize, SMEM_TOTAL);

    norm_kernel<<<NROWS / 8, 256>>>(a, b);
    dim3 grid(NROWS / BM, CGRPS);
    gemm_kernel<<<grid, 256, SMEM_TOTAL>>>((float*)d_out);
}